// round 13
// baseline (speedup 1.0000x reference)
#include <cuda_runtime.h>
#include <cstdint>

#define H_CH 256
#define NST  64
#define LL   4096
#define NBATCH 16

typedef unsigned long long ull;

// Scratch (device global: allocation-free rule)
__device__ float2 g_Khat[H_CH * LL];   // hermitian part of K, pre-scaled by 1/L

__device__ __forceinline__ float2 cmul(float2 a, float2 b) {
    return make_float2(a.x * b.x - a.y * b.y, a.x * b.y + a.y * b.x);
}
__device__ __forceinline__ float2 cadd(float2 a, float2 b) {
    return make_float2(a.x + b.x, a.y + b.y);
}
__device__ __forceinline__ float2 csub(float2 a, float2 b) {
    return make_float2(a.x - b.x, a.y - b.y);
}

// ---- packed f32x2 helpers ----
__device__ __forceinline__ ull pk(float lo, float hi) {
    ull r; asm("mov.b64 %0,{%1,%2};" : "=l"(r) : "f"(lo), "f"(hi)); return r;
}
__device__ __forceinline__ void upk(ull v, float& lo, float& hi) {
    asm("mov.b64 {%0,%1},%2;" : "=f"(lo), "=f"(hi) : "l"(v));
}
__device__ __forceinline__ ull fma2(ull a, ull b, ull c) {
    ull d; asm("fma.rn.f32x2 %0,%1,%2,%3;" : "=l"(d) : "l"(a), "l"(b), "l"(c)); return d;
}
__device__ __forceinline__ ull add2(ull a, ull b) {
    ull d; asm("add.rn.f32x2 %0,%1,%2;" : "=l"(d) : "l"(a), "l"(b)); return d;
}
__device__ __forceinline__ ull mul2(ull a, ull b) {
    ull d; asm("mul.rn.f32x2 %0,%1,%2;" : "=l"(d) : "l"(a), "l"(b)); return d;
}

// Correctly-rounded float sin/cos via double polynomial.
// Needed so 1+cos / 1-cos cancellation sites match the float32 reference bitwise.
// Valid for ang in [-2*pi, 0].
__device__ __forceinline__ void sincos_acc(float angf, float* s, float* c) {
    double x  = (double)angf;
    double kd = rint(x * 0.63661977236758134308);   // x / (pi/2)
    double r  = x - kd * 1.5707963267948966;
    r        -= kd * 6.123233995736766e-17;
    int q = (int)kd;
    double r2 = r * r;
    double sr = r * (1.0 + r2 * (-1.6666666666666666e-01 + r2 * (8.3333333333333332e-03
                 + r2 * (-1.9841269841269841e-04 + r2 * 2.7557319223985893e-06))));
    double cr = 1.0 + r2 * (-0.5 + r2 * (4.1666666666666664e-02
                 + r2 * (-1.3888888888888889e-03 + r2 * (2.4801587301587302e-05
                 - r2 * 2.7557319223985888e-07))));
    double ss, cc;
    switch (q & 3) {
        case 0:  ss =  sr; cc =  cr; break;
        case 1:  ss =  cr; cc = -sr; break;
        case 2:  ss = -sr; cc = -cr; break;
        default: ss = -cr; cc =  sr; break;
    }
    *s = (float)ss;
    *c = (float)cc;
}

// ---------------------------------------------------------------------------
// Kernel 1: S4 DPLR frequency-domain kernel + FUSED Hermitian part.
// (R9-measured-best version — kgen is fma-pipe-throughput bound; unchanged.)
// ---------------------------------------------------------------------------
__global__ __launch_bounds__(256)
void kgen(const float* __restrict__ Lre, const float* __restrict__ Lim,
          const float* __restrict__ Pre, const float* __restrict__ Pim,
          const float* __restrict__ Bre, const float* __restrict__ Bim,
          const float* __restrict__ Cre, const float* __restrict__ Cim,
          const float* __restrict__ lstep) {
    __shared__ float4 sA[NST];  // (-lam.re, -lam.im, pp, pp)       pp = |P|^2
    __shared__ float4 sB[NST];  // (cb.x, cb.x, cb.y, cb.y)   cb = conj(C)*B
    __shared__ float4 sC[NST];  // (cp.x, cp.x, cp.y, cp.y)   cp = conj(C)*P
    __shared__ float4 sD[NST];  // (pb.x, pb.x, pb.y, pb.y)   pb = conj(P)*B
    __shared__ float  s_tos;

    int h   = blockIdx.x >> 3;
    int seg = blockIdx.x & 7;
    int tid = threadIdx.x;

    if (tid < NST) {
        int idx = h * NST + tid;
        float lr = Lre[idx], li = Lim[idx];
        float pr = Pre[idx], pi = Pim[idx];
        float br = Bre[idx], bi = Bim[idx];
        float cr = Cre[idx], ci = Cim[idx];
        float cbx = cr * br + ci * bi, cby = cr * bi - ci * br;
        float cpx = cr * pr + ci * pi, cpy = cr * pi - ci * pr;
        float pbx = pr * br + pi * bi, pby = pr * bi - pi * br;
        float pp  = pr * pr + pi * pi;
        sA[tid] = make_float4(-lr, -li, pp, pp);
        sB[tid] = make_float4(cbx, cbx, cby, cby);
        sC[tid] = make_float4(cpx, cpx, cpy, cpy);
        sD[tid] = make_float4(pbx, pbx, pby, pby);
    }
    if (tid == 0) s_tos = 2.0f / __expf(lstep[h]);
    __syncthreads();
    float tos = s_tos;

    const float neg2pi = (float)(-6.283185307179586);

    // mirror-pair l mapping: (gid, 4096-gid); gid==0 -> (0, 2048)
    int gid = seg * 256 + tid;          // 0..2047 per h
    int lv[2];
    lv[0] = gid;
    lv[1] = (gid == 0) ? 2048 : (LL - gid);
    bool selfm = (gid == 0);            // both bins self-mirrored

    float crv[2], civ[2];               // c = 2/(1+Omega)
    ull   gpk[2];
    #pragma unroll
    for (int ii = 0; ii < 2; ++ii) {
        int l = lv[ii];
        float ang = neg2pi * ((float)l * (1.0f / 4096.0f));
        float so, co;
        sincos_acc(ang, &so, &co);
        float opr = 1.0f + co, opi = so;     // 1 + Omega (exact subtraction sites)
        float omr = 1.0f - co, omi = -so;    // 1 - Omega
        float rinv = __fdividef(1.0f, opr * opr + opi * opi);
        crv[ii] =  2.0f * opr * rinv;
        civ[ii] = -2.0f * opi * rinv;
        float gr = tos * ((omr * opr + omi * opi) * rinv);
        float gi = tos * ((omi * opr - omr * opi) * rinv);
        gpk[ii] = pk(gr, gi);
    }

    // packed accumulators: per l, per sum: A (x-table) and B (y-table)
    ull aA0[2] = {0,0}, aB0[2] = {0,0};   // k00
    ull aA1[2] = {0,0}, aB1[2] = {0,0};   // k01
    ull aA2[2] = {0,0}, aB2[2] = {0,0};   // k10
    ull a11[2] = {0,0};                   // k11 (pp,pp)*w

    #pragma unroll 8
    for (int n = 0; n < NST; ++n) {
        float4 fa = sA[n], fb = sB[n], fc = sC[n], fd = sD[n];
        ull nlam = pk(fa.x, fa.y);
        ull pp2  = pk(fa.z, fa.w);
        ull bx   = pk(fb.x, fb.y), by = pk(fb.z, fb.w);
        ull cx   = pk(fc.x, fc.y), cy = pk(fc.z, fc.w);
        ull dx   = pk(fd.x, fd.y), dy = pk(fd.z, fd.w);
        #pragma unroll
        for (int ii = 0; ii < 2; ++ii) {
            ull d = add2(gpk[ii], nlam);         // d = g - lambda  (dr, di)
            ull sq = mul2(d, d);                 // (dr^2, di^2)
            float s0, s1; upk(sq, s0, s1);
            float inv = __fdividef(1.0f, s0 + s1);
            ull w = mul2(d, pk(inv, inv));       // w = (p, q); 1/d = p - i*q
            aA0[ii] = fma2(bx, w, aA0[ii]);
            aB0[ii] = fma2(by, w, aB0[ii]);
            aA1[ii] = fma2(cx, w, aA1[ii]);
            aB1[ii] = fma2(cy, w, aB1[ii]);
            aA2[ii] = fma2(dx, w, aA2[ii]);
            aB2[ii] = fma2(dy, w, aB2[ii]);
            a11[ii] = fma2(pp2, w, a11[ii]);
        }
    }

    float2 kout[2];
    #pragma unroll
    for (int ii = 0; ii < 2; ++ii) {
        float xA, xB, yA, yB;
        // k00
        upk(aA0[ii], xA, xB); upk(aB0[ii], yA, yB);
        float a00r = xA + yB, a00i = yA - xB;
        // k01
        upk(aA1[ii], xA, xB); upk(aB1[ii], yA, yB);
        float a01r = xA + yB, a01i = yA - xB;
        // k10
        upk(aA2[ii], xA, xB); upk(aB2[ii], yA, yB);
        float a10r = xA + yB, a10i = yA - xB;
        // k11 = (acc.lo, -acc.hi)
        upk(a11[ii], xA, xB);
        float a11r = xA, a11i = -xB;

        // K = c * (k00 - k01 * k10 / (1 + k11))
        float tr = 1.0f + a11r, ti = a11i;
        float tinv = __fdividef(1.0f, tr * tr + ti * ti);
        float mr = a01r * a10r - a01i * a10i;
        float mi = a01r * a10i + a01i * a10r;
        float qr = (mr * tr + mi * ti) * tinv;
        float qi = (mi * tr - mr * ti) * tinv;
        float kr = a00r - qr, ki = a00i - qi;
        float cr_ = crv[ii], ci_ = civ[ii];
        kout[ii] = make_float2(cr_ * kr - ci_ * ki, cr_ * ki + ci_ * kr);
    }

    // Fused Hermitian part: Khat[l] = (K[l] + conj(K[-l])) * 0.5/L
    const float sc = 0.5f / 4096.0f;
    float2* Kh = g_Khat + ((size_t)h << 12);
    if (selfm) {
        Kh[lv[0]] = make_float2(2.0f * kout[0].x * sc, 0.0f);
        Kh[lv[1]] = make_float2(2.0f * kout[1].x * sc, 0.0f);
    } else {
        Kh[lv[0]] = make_float2((kout[0].x + kout[1].x) * sc,
                                (kout[0].y - kout[1].y) * sc);
        Kh[lv[1]] = make_float2((kout[1].x + kout[0].x) * sc,
                                (kout[1].y - kout[0].y) * sc);
    }
}

// ---------------------------------------------------------------------------
// Kernel 2: packed FFT convolution, radix-16 Stockham (4096 = 16^3, 3 stages).
// 256 threads x 16 points. Register-fused ends: gmem->fwd0; fwd2+Khat+inv0
// (stage 2 has p=0 -> natural order, no twiddle); inv2->gmem.
// Only 4 smem write+read rounds, 4 syncs (was 6W+6R, 6 syncs at radix-8).
// XOR swizzle SW(i) = i ^ ((i>>4) & 15): bijective on [0,4096), conflict-free
// for every pattern here (reads j+256r; writes 16j+r; writes q+256p+16r).
// ---------------------------------------------------------------------------
#define SW(i) ((i) ^ (((i) >> 4) & 15))
#define NPAD 4096

template <int DIR>
__device__ __forceinline__ void dft4o(float2 a, float2 b, float2 c, float2 d,
                                      float2& o0, float2& o1, float2& o2, float2& o3) {
    const float D = (float)DIR;
    float2 t0 = cadd(a, c), t1 = csub(a, c);
    float2 t2 = cadd(b, d);
    float2 bd = csub(b, d);
    float2 t3 = make_float2(-D * bd.y, D * bd.x);   // iD*(b-d)
    o0 = cadd(t0, t2);
    o1 = cadd(t1, t3);
    o2 = csub(t0, t2);
    o3 = csub(t1, t3);
}

template <int DIR>
__device__ __forceinline__ void dft16(const float2* x, float2* out) {
    const float D = (float)DIR;
    float2 A[4][4];
    #pragma unroll
    for (int n2 = 0; n2 < 4; ++n2)
        dft4o<DIR>(x[n2], x[4 + n2], x[8 + n2], x[12 + n2],
                   A[n2][0], A[n2][1], A[n2][2], A[n2][3]);

    const float C16 = 0.9238795325112867f;
    const float S16 = 0.3826834323650898f;
    const float C8  = 0.7071067811865476f;
    float2 W1 = make_float2(C16, D * S16);
    float2 W2 = make_float2(C8,  D * C8);
    float2 W3 = make_float2(S16, D * C16);
    float2 W6 = make_float2(-C8, D * C8);
    float2 W9 = make_float2(-C16, -D * S16);
    A[1][1] = cmul(A[1][1], W1);
    A[1][2] = cmul(A[1][2], W2);
    A[1][3] = cmul(A[1][3], W3);
    A[2][1] = cmul(A[2][1], W2);
    { float2 t = A[2][2]; A[2][2] = make_float2(-D * t.y, D * t.x); }  // *(0,D)
    A[2][3] = cmul(A[2][3], W6);
    A[3][1] = cmul(A[3][1], W3);
    A[3][2] = cmul(A[3][2], W6);
    A[3][3] = cmul(A[3][3], W9);

    #pragma unroll
    for (int k1 = 0; k1 < 4; ++k1)
        dft4o<DIR>(A[0][k1], A[1][k1], A[2][k1], A[3][k1],
                   out[k1], out[k1 + 4], out[k1 + 8], out[k1 + 12]);
}

template <int DIR, int K>
__device__ __forceinline__ void twiddle16(float2* out, int p) {
    if (K < 2) {
        const float base = (float)DIR * 6.2831853071795864f / (float)(4096 >> (4 * K));
        float sn, cs;
        __sincosf(base * (float)p, &sn, &cs);
        float2 w = make_float2(cs, sn);
        float2 acc = w;
        #pragma unroll
        for (int r = 1; r < 16; ++r) {
            out[r] = cmul(out[r], acc);
            if (r < 15) acc = cmul(acc, w);
        }
    }
}

// middle stage k=1: smem -> smem
template <int DIR>
__device__ __forceinline__ void stage16_smem(const float2* X, float2* Y, int j) {
    float2 x[16];
    #pragma unroll
    for (int r = 0; r < 16; ++r) x[r] = X[SW(j + 256 * r)];
    float2 out[16];
    dft16<DIR>(x, out);
    int p = j >> 4, q = j & 15;
    twiddle16<DIR, 1>(out, p);
    int wb = q + 256 * p;                 // q + 16*s*p with s=16
    #pragma unroll
    for (int r = 0; r < 16; ++r) Y[SW(wb + 16 * r)] = out[r];
}

__global__ __launch_bounds__(256)
void fftconv(const float* __restrict__ u, float* __restrict__ y) {
    extern __shared__ float2 smem[];
    float2* B0 = smem;
    float2* B1 = smem + NPAD;
    int j  = threadIdx.x;                 // 0..255
    int h  = blockIdx.x & 255;
    int pb = blockIdx.x >> 8;

    size_t off0 = ((size_t)(2 * pb) * H_CH + (size_t)h) * LL;
    const float* u0 = u + off0;
    const float* u1 = u0 + (size_t)H_CH * LL;

    // fused: gmem load + forward stage 0 (regs) -> smem
    {
        float2 x[16], out[16];
        #pragma unroll
        for (int r = 0; r < 16; ++r) {
            int i = j + 256 * r;
            x[r] = make_float2(u0[i], u1[i]);
        }
        dft16<-1>(x, out);
        twiddle16<-1, 0>(out, j);
        #pragma unroll
        for (int r = 0; r < 16; ++r) B0[SW(16 * j + r)] = out[r];
    }
    __syncthreads();
    stage16_smem<-1>(B0, B1, j);
    __syncthreads();

    // fused: forward stage 2 (p=0, natural order, no twiddle) + Khat multiply
    // + inverse stage 0 (all in regs) -> smem
    {
        float2 x[16], f[16], out[16];
        #pragma unroll
        for (int r = 0; r < 16; ++r) x[r] = B1[SW(j + 256 * r)];
        dft16<-1>(x, f);
        const float2* Kh = g_Khat + ((size_t)h << 12);
        #pragma unroll
        for (int r = 0; r < 16; ++r) f[r] = cmul(f[r], Kh[j + 256 * r]);
        dft16<1>(f, out);
        twiddle16<1, 0>(out, j);
        #pragma unroll
        for (int r = 0; r < 16; ++r) B0[SW(16 * j + r)] = out[r];
    }
    __syncthreads();
    stage16_smem<1>(B0, B1, j);
    __syncthreads();

    // fused: inverse stage 2 (regs) -> gmem (natural order, coalesced)
    {
        float2 x[16], out[16];
        #pragma unroll
        for (int r = 0; r < 16; ++r) x[r] = B1[SW(j + 256 * r)];
        dft16<1>(x, out);
        float* y0 = y + off0;
        float* y1 = y0 + (size_t)H_CH * LL;
        #pragma unroll
        for (int r = 0; r < 16; ++r) {
            int i = j + 256 * r;
            y0[i] = out[r].x;
            y1[i] = out[r].y;
        }
    }
}

// ---------------------------------------------------------------------------
extern "C" void kernel_launch(void* const* d_in, const int* in_sizes, int n_in,
                              void* d_out, int out_size) {
    (void)in_sizes; (void)n_in; (void)out_size;
    const float* u   = (const float*)d_in[0];
    const float* Lre = (const float*)d_in[1];
    const float* Lim = (const float*)d_in[2];
    const float* Pre = (const float*)d_in[3];
    const float* Pim = (const float*)d_in[4];
    const float* Bre = (const float*)d_in[5];
    const float* Bim = (const float*)d_in[6];
    const float* Cre = (const float*)d_in[7];
    const float* Cim = (const float*)d_in[8];
    const float* lst = (const float*)d_in[9];
    float* y = (float*)d_out;

    const int smem_bytes = 2 * NPAD * (int)sizeof(float2);  // 65536
    cudaFuncSetAttribute(fftconv, cudaFuncAttributeMaxDynamicSharedMemorySize, smem_bytes);

    kgen<<<H_CH * 8, 256>>>(Lre, Lim, Pre, Pim, Bre, Bim, Cre, Cim, lst);
    fftconv<<<(NBATCH / 2) * H_CH, 256, smem_bytes>>>(u, y);
}

// round 14
// speedup vs baseline: 1.0380x; 1.0380x over previous
#include <cuda_runtime.h>
#include <cstdint>

#define H_CH 256
#define NST  64
#define LL   4096
#define NBATCH 16

typedef unsigned long long ull;

// Scratch (device global: allocation-free rule)
__device__ float2 g_Khat[H_CH * LL];   // hermitian part of K, pre-scaled by 1/L

__device__ __forceinline__ float2 cmul(float2 a, float2 b) {
    return make_float2(a.x * b.x - a.y * b.y, a.x * b.y + a.y * b.x);
}
__device__ __forceinline__ float2 cadd(float2 a, float2 b) {
    return make_float2(a.x + b.x, a.y + b.y);
}
__device__ __forceinline__ float2 csub(float2 a, float2 b) {
    return make_float2(a.x - b.x, a.y - b.y);
}

// ---- packed f32x2 helpers ----
__device__ __forceinline__ ull pk(float lo, float hi) {
    ull r; asm("mov.b64 %0,{%1,%2};" : "=l"(r) : "f"(lo), "f"(hi)); return r;
}
__device__ __forceinline__ void upk(ull v, float& lo, float& hi) {
    asm("mov.b64 {%0,%1},%2;" : "=f"(lo), "=f"(hi) : "l"(v));
}
__device__ __forceinline__ ull fma2(ull a, ull b, ull c) {
    ull d; asm("fma.rn.f32x2 %0,%1,%2,%3;" : "=l"(d) : "l"(a), "l"(b), "l"(c)); return d;
}
__device__ __forceinline__ ull add2(ull a, ull b) {
    ull d; asm("add.rn.f32x2 %0,%1,%2;" : "=l"(d) : "l"(a), "l"(b)); return d;
}
__device__ __forceinline__ ull mul2(ull a, ull b) {
    ull d; asm("mul.rn.f32x2 %0,%1,%2;" : "=l"(d) : "l"(a), "l"(b)); return d;
}

// Correctly-rounded float sin/cos via double polynomial.
// Needed so 1+cos / 1-cos cancellation sites match the float32 reference bitwise.
// Valid for ang in [-2*pi, 0].
__device__ __forceinline__ void sincos_acc(float angf, float* s, float* c) {
    double x  = (double)angf;
    double kd = rint(x * 0.63661977236758134308);   // x / (pi/2)
    double r  = x - kd * 1.5707963267948966;
    r        -= kd * 6.123233995736766e-17;
    int q = (int)kd;
    double r2 = r * r;
    double sr = r * (1.0 + r2 * (-1.6666666666666666e-01 + r2 * (8.3333333333333332e-03
                 + r2 * (-1.9841269841269841e-04 + r2 * 2.7557319223985893e-06))));
    double cr = 1.0 + r2 * (-0.5 + r2 * (4.1666666666666664e-02
                 + r2 * (-1.3888888888888889e-03 + r2 * (2.4801587301587302e-05
                 - r2 * 2.7557319223985888e-07))));
    double ss, cc;
    switch (q & 3) {
        case 0:  ss =  sr; cc =  cr; break;
        case 1:  ss =  cr; cc = -sr; break;
        case 2:  ss = -sr; cc = -cr; break;
        default: ss = -cr; cc =  sr; break;
    }
    *s = (float)ss;
    *c = (float)cc;
}

// ---------------------------------------------------------------------------
// Kernel 1: S4 DPLR frequency-domain kernel + FUSED Hermitian part.
// (R9-measured-best version — kgen is fma-pipe-throughput bound; unchanged.)
// ---------------------------------------------------------------------------
__global__ __launch_bounds__(256)
void kgen(const float* __restrict__ Lre, const float* __restrict__ Lim,
          const float* __restrict__ Pre, const float* __restrict__ Pim,
          const float* __restrict__ Bre, const float* __restrict__ Bim,
          const float* __restrict__ Cre, const float* __restrict__ Cim,
          const float* __restrict__ lstep) {
    __shared__ float4 sA[NST];  // (-lam.re, -lam.im, pp, pp)       pp = |P|^2
    __shared__ float4 sB[NST];  // (cb.x, cb.x, cb.y, cb.y)   cb = conj(C)*B
    __shared__ float4 sC[NST];  // (cp.x, cp.x, cp.y, cp.y)   cp = conj(C)*P
    __shared__ float4 sD[NST];  // (pb.x, pb.x, pb.y, pb.y)   pb = conj(P)*B
    __shared__ float  s_tos;

    int h   = blockIdx.x >> 3;
    int seg = blockIdx.x & 7;
    int tid = threadIdx.x;

    if (tid < NST) {
        int idx = h * NST + tid;
        float lr = Lre[idx], li = Lim[idx];
        float pr = Pre[idx], pi = Pim[idx];
        float br = Bre[idx], bi = Bim[idx];
        float cr = Cre[idx], ci = Cim[idx];
        float cbx = cr * br + ci * bi, cby = cr * bi - ci * br;
        float cpx = cr * pr + ci * pi, cpy = cr * pi - ci * pr;
        float pbx = pr * br + pi * bi, pby = pr * bi - pi * br;
        float pp  = pr * pr + pi * pi;
        sA[tid] = make_float4(-lr, -li, pp, pp);
        sB[tid] = make_float4(cbx, cbx, cby, cby);
        sC[tid] = make_float4(cpx, cpx, cpy, cpy);
        sD[tid] = make_float4(pbx, pbx, pby, pby);
    }
    if (tid == 0) s_tos = 2.0f / __expf(lstep[h]);
    __syncthreads();
    float tos = s_tos;

    const float neg2pi = (float)(-6.283185307179586);

    // mirror-pair l mapping: (gid, 4096-gid); gid==0 -> (0, 2048)
    int gid = seg * 256 + tid;          // 0..2047 per h
    int lv[2];
    lv[0] = gid;
    lv[1] = (gid == 0) ? 2048 : (LL - gid);
    bool selfm = (gid == 0);            // both bins self-mirrored

    float crv[2], civ[2];               // c = 2/(1+Omega)
    ull   gpk[2];
    #pragma unroll
    for (int ii = 0; ii < 2; ++ii) {
        int l = lv[ii];
        float ang = neg2pi * ((float)l * (1.0f / 4096.0f));
        float so, co;
        sincos_acc(ang, &so, &co);
        float opr = 1.0f + co, opi = so;     // 1 + Omega (exact subtraction sites)
        float omr = 1.0f - co, omi = -so;    // 1 - Omega
        float rinv = __fdividef(1.0f, opr * opr + opi * opi);
        crv[ii] =  2.0f * opr * rinv;
        civ[ii] = -2.0f * opi * rinv;
        float gr = tos * ((omr * opr + omi * opi) * rinv);
        float gi = tos * ((omi * opr - omr * opi) * rinv);
        gpk[ii] = pk(gr, gi);
    }

    // packed accumulators: per l, per sum: A (x-table) and B (y-table)
    ull aA0[2] = {0,0}, aB0[2] = {0,0};   // k00
    ull aA1[2] = {0,0}, aB1[2] = {0,0};   // k01
    ull aA2[2] = {0,0}, aB2[2] = {0,0};   // k10
    ull a11[2] = {0,0};                   // k11 (pp,pp)*w

    #pragma unroll 8
    for (int n = 0; n < NST; ++n) {
        float4 fa = sA[n], fb = sB[n], fc = sC[n], fd = sD[n];
        ull nlam = pk(fa.x, fa.y);
        ull pp2  = pk(fa.z, fa.w);
        ull bx   = pk(fb.x, fb.y), by = pk(fb.z, fb.w);
        ull cx   = pk(fc.x, fc.y), cy = pk(fc.z, fc.w);
        ull dx   = pk(fd.x, fd.y), dy = pk(fd.z, fd.w);
        #pragma unroll
        for (int ii = 0; ii < 2; ++ii) {
            ull d = add2(gpk[ii], nlam);         // d = g - lambda  (dr, di)
            ull sq = mul2(d, d);                 // (dr^2, di^2)
            float s0, s1; upk(sq, s0, s1);
            float inv = __fdividef(1.0f, s0 + s1);
            ull w = mul2(d, pk(inv, inv));       // w = (p, q); 1/d = p - i*q
            aA0[ii] = fma2(bx, w, aA0[ii]);
            aB0[ii] = fma2(by, w, aB0[ii]);
            aA1[ii] = fma2(cx, w, aA1[ii]);
            aB1[ii] = fma2(cy, w, aB1[ii]);
            aA2[ii] = fma2(dx, w, aA2[ii]);
            aB2[ii] = fma2(dy, w, aB2[ii]);
            a11[ii] = fma2(pp2, w, a11[ii]);
        }
    }

    float2 kout[2];
    #pragma unroll
    for (int ii = 0; ii < 2; ++ii) {
        float xA, xB, yA, yB;
        // k00
        upk(aA0[ii], xA, xB); upk(aB0[ii], yA, yB);
        float a00r = xA + yB, a00i = yA - xB;
        // k01
        upk(aA1[ii], xA, xB); upk(aB1[ii], yA, yB);
        float a01r = xA + yB, a01i = yA - xB;
        // k10
        upk(aA2[ii], xA, xB); upk(aB2[ii], yA, yB);
        float a10r = xA + yB, a10i = yA - xB;
        // k11 = (acc.lo, -acc.hi)
        upk(a11[ii], xA, xB);
        float a11r = xA, a11i = -xB;

        // K = c * (k00 - k01 * k10 / (1 + k11))
        float tr = 1.0f + a11r, ti = a11i;
        float tinv = __fdividef(1.0f, tr * tr + ti * ti);
        float mr = a01r * a10r - a01i * a10i;
        float mi = a01r * a10i + a01i * a10r;
        float qr = (mr * tr + mi * ti) * tinv;
        float qi = (mi * tr - mr * ti) * tinv;
        float kr = a00r - qr, ki = a00i - qi;
        float cr_ = crv[ii], ci_ = civ[ii];
        kout[ii] = make_float2(cr_ * kr - ci_ * ki, cr_ * ki + ci_ * kr);
    }

    // Fused Hermitian part: Khat[l] = (K[l] + conj(K[-l])) * 0.5/L
    const float sc = 0.5f / 4096.0f;
    float2* Kh = g_Khat + ((size_t)h << 12);
    if (selfm) {
        Kh[lv[0]] = make_float2(2.0f * kout[0].x * sc, 0.0f);
        Kh[lv[1]] = make_float2(2.0f * kout[1].x * sc, 0.0f);
    } else {
        Kh[lv[0]] = make_float2((kout[0].x + kout[1].x) * sc,
                                (kout[0].y - kout[1].y) * sc);
        Kh[lv[1]] = make_float2((kout[1].x + kout[0].x) * sc,
                                (kout[1].y - kout[0].y) * sc);
    }
}

// ---------------------------------------------------------------------------
// Kernel 2: packed FFT convolution, radix-16 Stockham (4096 = 16^3, 3 stages).
// 256 threads x 16 points. Register-fused ends. 4 smem rounds, 4 syncs.
// THIS ROUND: __launch_bounds__(256,3) to force >=3 CTAs/SM (R13 had regs=99
// -> occ 23.8%, latency-bound), + binary-power twiddles (chain depth 15 -> 4).
// XOR swizzle SW(i) = i ^ ((i>>4) & 15): bijective, conflict-free for all
// patterns here (reads j+256r; writes 16j+r; writes q+256p+16r).
// ---------------------------------------------------------------------------
#define SW(i) ((i) ^ (((i) >> 4) & 15))
#define NPAD 4096

template <int DIR>
__device__ __forceinline__ void dft4o(float2 a, float2 b, float2 c, float2 d,
                                      float2& o0, float2& o1, float2& o2, float2& o3) {
    const float D = (float)DIR;
    float2 t0 = cadd(a, c), t1 = csub(a, c);
    float2 t2 = cadd(b, d);
    float2 bd = csub(b, d);
    float2 t3 = make_float2(-D * bd.y, D * bd.x);   // iD*(b-d)
    o0 = cadd(t0, t2);
    o1 = cadd(t1, t3);
    o2 = csub(t0, t2);
    o3 = csub(t1, t3);
}

template <int DIR>
__device__ __forceinline__ void dft16(const float2* x, float2* out) {
    const float D = (float)DIR;
    float2 A[4][4];
    #pragma unroll
    for (int n2 = 0; n2 < 4; ++n2)
        dft4o<DIR>(x[n2], x[4 + n2], x[8 + n2], x[12 + n2],
                   A[n2][0], A[n2][1], A[n2][2], A[n2][3]);

    const float C16 = 0.9238795325112867f;
    const float S16 = 0.3826834323650898f;
    const float C8  = 0.7071067811865476f;
    float2 W1 = make_float2(C16, D * S16);
    float2 W2 = make_float2(C8,  D * C8);
    float2 W3 = make_float2(S16, D * C16);
    float2 W6 = make_float2(-C8, D * C8);
    float2 W9 = make_float2(-C16, -D * S16);
    A[1][1] = cmul(A[1][1], W1);
    A[1][2] = cmul(A[1][2], W2);
    A[1][3] = cmul(A[1][3], W3);
    A[2][1] = cmul(A[2][1], W2);
    { float2 t = A[2][2]; A[2][2] = make_float2(-D * t.y, D * t.x); }  // *(0,D)
    A[2][3] = cmul(A[2][3], W6);
    A[3][1] = cmul(A[3][1], W3);
    A[3][2] = cmul(A[3][2], W6);
    A[3][3] = cmul(A[3][3], W9);

    #pragma unroll
    for (int k1 = 0; k1 < 4; ++k1)
        dft4o<DIR>(A[0][k1], A[1][k1], A[2][k1], A[3][k1],
                   out[k1], out[k1 + 4], out[k1 + 8], out[k1 + 12]);
}

// twiddle powers via binary powering: dependency depth ~4 instead of 15
template <int DIR, int K>
__device__ __forceinline__ void twiddle16(float2* out, int p) {
    if (K < 2) {
        const float base = (float)DIR * 6.2831853071795864f / (float)(4096 >> (4 * K));
        float sn, cs;
        __sincosf(base * (float)p, &sn, &cs);
        float2 w[16];
        w[1] = make_float2(cs, sn);
        w[2] = cmul(w[1], w[1]);
        w[3] = cmul(w[2], w[1]);
        w[4] = cmul(w[2], w[2]);
        w[5] = cmul(w[4], w[1]);
        w[6] = cmul(w[4], w[2]);
        w[7] = cmul(w[4], w[3]);
        w[8] = cmul(w[4], w[4]);
        w[9]  = cmul(w[8], w[1]);
        w[10] = cmul(w[8], w[2]);
        w[11] = cmul(w[8], w[3]);
        w[12] = cmul(w[8], w[4]);
        w[13] = cmul(w[8], w[5]);
        w[14] = cmul(w[8], w[6]);
        w[15] = cmul(w[8], w[7]);
        #pragma unroll
        for (int r = 1; r < 16; ++r) out[r] = cmul(out[r], w[r]);
    }
}

// middle stage k=1: smem -> smem
template <int DIR>
__device__ __forceinline__ void stage16_smem(const float2* X, float2* Y, int j) {
    float2 x[16];
    #pragma unroll
    for (int r = 0; r < 16; ++r) x[r] = X[SW(j + 256 * r)];
    float2 out[16];
    dft16<DIR>(x, out);
    int p = j >> 4, q = j & 15;
    twiddle16<DIR, 1>(out, p);
    int wb = q + 256 * p;                 // q + 16*s*p with s=16
    #pragma unroll
    for (int r = 0; r < 16; ++r) Y[SW(wb + 16 * r)] = out[r];
}

__global__ __launch_bounds__(256, 3)
void fftconv(const float* __restrict__ u, float* __restrict__ y) {
    extern __shared__ float2 smem[];
    float2* B0 = smem;
    float2* B1 = smem + NPAD;
    int j  = threadIdx.x;                 // 0..255
    int h  = blockIdx.x & 255;
    int pb = blockIdx.x >> 8;

    size_t off0 = ((size_t)(2 * pb) * H_CH + (size_t)h) * LL;
    const float* u0 = u + off0;
    const float* u1 = u0 + (size_t)H_CH * LL;

    // fused: gmem load + forward stage 0 (regs) -> smem
    {
        float2 x[16];
        #pragma unroll
        for (int r = 0; r < 16; ++r) {
            int i = j + 256 * r;
            x[r] = make_float2(u0[i], u1[i]);
        }
        float2 out[16];
        dft16<-1>(x, out);
        twiddle16<-1, 0>(out, j);
        #pragma unroll
        for (int r = 0; r < 16; ++r) B0[SW(16 * j + r)] = out[r];
    }
    __syncthreads();
    stage16_smem<-1>(B0, B1, j);
    __syncthreads();

    // fused: forward stage 2 (p=0, natural order, no twiddle) + Khat multiply
    // + inverse stage 0 (all in regs) -> smem
    {
        float2 f[16];
        {
            float2 x[16];
            #pragma unroll
            for (int r = 0; r < 16; ++r) x[r] = B1[SW(j + 256 * r)];
            dft16<-1>(x, f);
        }
        const float2* Kh = g_Khat + ((size_t)h << 12);
        #pragma unroll
        for (int r = 0; r < 16; ++r) f[r] = cmul(f[r], Kh[j + 256 * r]);
        float2 out[16];
        dft16<1>(f, out);
        twiddle16<1, 0>(out, j);
        #pragma unroll
        for (int r = 0; r < 16; ++r) B0[SW(16 * j + r)] = out[r];
    }
    __syncthreads();
    stage16_smem<1>(B0, B1, j);
    __syncthreads();

    // fused: inverse stage 2 (regs) -> gmem (natural order, coalesced)
    {
        float2 x[16];
        #pragma unroll
        for (int r = 0; r < 16; ++r) x[r] = B1[SW(j + 256 * r)];
        float2 out[16];
        dft16<1>(x, out);
        float* y0 = y + off0;
        float* y1 = y0 + (size_t)H_CH * LL;
        #pragma unroll
        for (int r = 0; r < 16; ++r) {
            int i = j + 256 * r;
            y0[i] = out[r].x;
            y1[i] = out[r].y;
        }
    }
}

// ---------------------------------------------------------------------------
extern "C" void kernel_launch(void* const* d_in, const int* in_sizes, int n_in,
                              void* d_out, int out_size) {
    (void)in_sizes; (void)n_in; (void)out_size;
    const float* u   = (const float*)d_in[0];
    const float* Lre = (const float*)d_in[1];
    const float* Lim = (const float*)d_in[2];
    const float* Pre = (const float*)d_in[3];
    const float* Pim = (const float*)d_in[4];
    const float* Bre = (const float*)d_in[5];
    const float* Bim = (const float*)d_in[6];
    const float* Cre = (const float*)d_in[7];
    const float* Cim = (const float*)d_in[8];
    const float* lst = (const float*)d_in[9];
    float* y = (float*)d_out;

    const int smem_bytes = 2 * NPAD * (int)sizeof(float2);  // 65536
    cudaFuncSetAttribute(fftconv, cudaFuncAttributeMaxDynamicSharedMemorySize, smem_bytes);

    kgen<<<H_CH * 8, 256>>>(Lre, Lim, Pre, Pim, Bre, Bim, Cre, Cim, lst);
    fftconv<<<(NBATCH / 2) * H_CH, 256, smem_bytes>>>(u, y);
}